// round 15
// baseline (speedup 1.0000x reference)
#include <cuda_runtime.h>
#include <cuda_fp16.h>
#include <cstdint>

#define D_IN    128
#define D_MAIN  256
#define D_BLOCK 512
#define N_CAND  100000
#define BATCH   1024
#define NTOT    (N_CAND + BATCH)
#define CTX     96
#define NSCR    1024         // max survivors per row
#define NROWS_T (BATCH * CTX)

typedef __half h16;

// ---------------------------------------------------------------------------
// Scratch (static __device__ — no allocations allowed)
// ---------------------------------------------------------------------------
__device__ float g_h1 [NTOT * D_MAIN];
__device__ float g_x2 [NTOT * D_MAIN];
__device__ float g_ck [NTOT * D_MAIN];
__device__ float g_cknorm[N_CAND];
__device__ h16   g_Sh [BATCH * (size_t)N_CAND];
__device__ float g_x3 [BATCH * D_MAIN];
__device__ float g_x4 [BATCH * D_MAIN];
__device__ int   g_scr[BATCH * NSCR];
__device__ int   g_scrcnt[BATCH];
__device__ int   g_idx[BATCH * CTX];
__device__ float g_probs[BATCH * CTX];
__device__ float g_y  [NROWS_T];
__device__ float g_ysum[BATCH];
__device__ float g_bfuse[D_BLOCK];

// fp16 split planes
__device__ h16 g_cxp [2][NTOT * D_IN];
__device__ h16 g_up  [2][NTOT * D_BLOCK];
__device__ h16 g_lnp [2][NTOT * D_MAIN];
__device__ h16 g_ckp [NTOT * D_MAIN];        // 1 plane (1-prod score)
__device__ h16 g_dfp [NROWS_T * D_MAIN];
__device__ h16 g_t1p [NROWS_T * D_BLOCK];
__device__ h16 g_Rp  [2][BATCH * D_BLOCK];
__device__ h16 g_ln2p[2][BATCH * D_MAIN];
__device__ h16 g_ptp [2][BATCH * D_BLOCK];

// weight planes, transposed to [N][K]
__device__ h16 g_wlin[2][D_MAIN * D_IN];
__device__ h16 g_wfuse[2][D_BLOCK * D_IN];
__device__ h16 g_wb02[2][D_MAIN * D_BLOCK];
__device__ h16 g_wK  [2][D_MAIN * D_MAIN];
__device__ h16 g_wT1 [2][D_BLOCK * D_MAIN];
__device__ h16 g_wT2 [2][D_MAIN * D_BLOCK];
__device__ h16 g_wp1 [2][D_BLOCK * D_MAIN];
__device__ h16 g_wp2 [2][D_MAIN * D_BLOCK];

// ---------------------------------------------------------------------------
// PTX helpers (sm_80+ — no 'a'-gated features)
// ---------------------------------------------------------------------------
__device__ __forceinline__ uint32_t smem_to_u32(const void* p) {
    uint32_t a;
    asm("{ .reg .u64 t; cvta.to.shared.u64 t, %1; cvt.u32.u64 %0, t; }"
        : "=r"(a) : "l"(p));
    return a;
}
__device__ __forceinline__ void ldsm_x4(uint32_t& r0, uint32_t& r1,
                                        uint32_t& r2, uint32_t& r3, uint32_t addr)
{
    asm volatile("ldmatrix.sync.aligned.m8n8.x4.shared.b16 {%0,%1,%2,%3}, [%4];"
                 : "=r"(r0), "=r"(r1), "=r"(r2), "=r"(r3) : "r"(addr));
}
__device__ __forceinline__ void mma16816(float* d, const uint32_t* a, const uint32_t* b)
{
    asm volatile("mma.sync.aligned.m16n8k16.row.col.f32.f16.f16.f32 "
                 "{%0,%1,%2,%3}, {%4,%5,%6,%7}, {%8,%9}, {%0,%1,%2,%3};"
                 : "+f"(d[0]), "+f"(d[1]), "+f"(d[2]), "+f"(d[3])
                 : "r"(a[0]), "r"(a[1]), "r"(a[2]), "r"(a[3]),
                   "r"(b[0]), "r"(b[1]));
}
__device__ __forceinline__ void cp_async16(uint32_t dst, const void* src, bool pred)
{
    int sz = pred ? 16 : 0;
    asm volatile("cp.async.cg.shared.global [%0], [%1], 16, %2;"
                 :: "r"(dst), "l"(src), "r"(sz) : "memory");
}
#define CP_COMMIT() asm volatile("cp.async.commit_group;" ::: "memory")
#define CP_WAIT1()  asm volatile("cp.async.wait_group 1;" ::: "memory")
#define CP_WAIT0()  asm volatile("cp.async.wait_group 0;" ::: "memory")

__device__ __forceinline__ void split2h(float x, h16& a, h16& b)
{
    a = __float2half_rn(x);
    b = __float2half_rn(x - __half2float(a));
}
__device__ __forceinline__ uint32_t ordkey(float f)
{
    uint32_t u = __float_as_uint(f);
    return (u & 0x80000000u) ? ~u : (u | 0x80000000u);
}
__device__ __forceinline__ uint32_t okey16u(uint16_t u)
{
    return (u & 0x8000u) ? (uint32_t)(0xFFFFu & ~u) : (uint32_t)(u | 0x8000u);
}
__device__ __forceinline__ void stcs_u32(void* p, uint32_t v)
{
    asm volatile("st.global.cs.u32 [%0], %1;" :: "l"(p), "r"(v) : "memory");
}

// ---------------------------------------------------------------------------
// HMMA split-fp16 GEMM: C[M,N] = A[M,K] @ B[N,K]^T.
// NPROD=3: a0b0+a0b1+a1b0 (~2^-22); NPROD=2: a0b0+a0b1 (~2^-11);
// NPROD=1: a0b0 (plain fp16, screening grade; OUTPL=1 uses streaming stores).
// 128x128 tile, 8 warps (4x2), warp tile 32x64, BK=32, 3-stage cp.async ring.
// Epilogue uses paired (half2/float2) stores; requires N even (always true).
// ---------------------------------------------------------------------------
enum { EPI_BIAS = 1, EPI_RELU = 2, EPI_RESID = 4, EPI_YLAB = 8, EPI_SCORE = 16 };

#define PLANE_BYTES 8192   // 128 rows * 64B

template <int NPROD, int EPI, int OUTF32, int OUTPL>
__global__ __launch_bounds__(256, 2)
void tgemm(const h16* __restrict__ A0, const h16* __restrict__ A1,
           const h16* __restrict__ B0, const h16* __restrict__ B1,
           float* __restrict__ C, h16* __restrict__ P0, h16* __restrict__ P1,
           int M, int N, int K,
           const float* __restrict__ bias, const float* __restrict__ resid,
           const float* __restrict__ rowscale, const float* __restrict__ vec)
{
    constexpr int NPA = (NPROD == 3) ? 2 : 1;
    constexpr int NPB = (NPROD >= 2) ? 2 : 1;
    constexpr int NPL = NPA + NPB;
    constexpr int STAGE = NPL * PLANE_BYTES;
    extern __shared__ __align__(16) char smem[];
    const uint32_t sb = smem_to_u32(smem);
    const int tid = threadIdx.x;
    const int wid = tid >> 5, lane = tid & 31;
    const int wm = wid & 3, wn = wid >> 2;
    const int m0 = blockIdx.y * 128, n0 = blockIdx.x * 128;

    const h16* Ap[2] = {A0, A1};
    const h16* Bp[2] = {B0, B1};

    float d[2][8][4];
#pragma unroll
    for (int i = 0; i < 2; i++)
#pragma unroll
        for (int j = 0; j < 8; j++)
#pragma unroll
            for (int e = 0; e < 4; e++) d[i][j][e] = 0.f;

    const int lrow = lane & 15;
    const int lhc  = lane >> 4;
    const int nch  = K >> 5;

    const int rA = tid >> 2, cA = tid & 3;
    auto load_tile = [&](int ch, int stg) {
        const int k0 = ch << 5;
        uint32_t base = sb + stg * STAGE;
#pragma unroll
        for (int it = 0; it < 2; it++) {
            int r = rA + it * 64;
            int sw = cA ^ ((r >> 1) & 3);
#pragma unroll
            for (int p = 0; p < NPA; p++) {
                int m = m0 + r;
                cp_async16(base + p * PLANE_BYTES + r * 64 + sw * 16,
                           Ap[p] + (size_t)m * K + k0 + cA * 8, m < M);
            }
#pragma unroll
            for (int q = 0; q < NPB; q++) {
                int n = n0 + r;
                cp_async16(base + (NPA + q) * PLANE_BYTES + r * 64 + sw * 16,
                           Bp[q] + (size_t)n * K + k0 + cA * 8, n < N);
            }
        }
    };

    load_tile(0, 0);
    CP_COMMIT();
    if (nch > 1) { load_tile(1, 1); CP_COMMIT(); }

    for (int ch = 0; ch < nch; ch++) {
        if (ch + 1 < nch) { CP_WAIT1(); } else { CP_WAIT0(); }
        __syncthreads();
        if (ch + 2 < nch) { load_tile(ch + 2, (ch + 2) % 3); CP_COMMIT(); }

        const uint32_t base = sb + (ch % 3) * STAGE;
#pragma unroll
        for (int ks = 0; ks < 2; ks++) {
            const int qc = ks * 2 + lhc;
            uint32_t a[NPA][2][4];
#pragma unroll
            for (int p = 0; p < NPA; p++)
#pragma unroll
                for (int mt = 0; mt < 2; mt++) {
                    int R = wm * 32 + mt * 16 + lrow;
                    int sw = qc ^ ((R >> 1) & 3);
                    ldsm_x4(a[p][mt][0], a[p][mt][1], a[p][mt][2], a[p][mt][3],
                            base + p * PLANE_BYTES + R * 64 + sw * 16);
                }
            uint32_t b[8][2];
#pragma unroll
            for (int ng = 0; ng < 4; ng++) {
                int R = wn * 64 + ng * 16 + lrow;
                int sw = qc ^ ((R >> 1) & 3);
                uint32_t q0, q1, q2, q3;
                ldsm_x4(q0, q1, q2, q3,
                        base + NPA * PLANE_BYTES + R * 64 + sw * 16);
                b[ng * 2 + 0][0] = q0; b[ng * 2 + 1][0] = q1;
                b[ng * 2 + 0][1] = q2; b[ng * 2 + 1][1] = q3;
            }
#pragma unroll
            for (int mt = 0; mt < 2; mt++)
#pragma unroll
                for (int nt = 0; nt < 8; nt++) {
                    mma16816(d[mt][nt], a[0][mt], b[nt]);
                    if (NPROD == 3) mma16816(d[mt][nt], a[1][mt], b[nt]);
                }
            if (NPROD >= 2) {
#pragma unroll
                for (int ng = 0; ng < 4; ng++) {
                    int R = wn * 64 + ng * 16 + lrow;
                    int sw = qc ^ ((R >> 1) & 3);
                    uint32_t q0, q1, q2, q3;
                    ldsm_x4(q0, q1, q2, q3,
                            base + (NPA + 1) * PLANE_BYTES + R * 64 + sw * 16);
                    b[ng * 2 + 0][0] = q0; b[ng * 2 + 1][0] = q1;
                    b[ng * 2 + 0][1] = q2; b[ng * 2 + 1][1] = q3;
                }
#pragma unroll
                for (int mt = 0; mt < 2; mt++)
#pragma unroll
                    for (int nt = 0; nt < 8; nt++)
                        mma16816(d[mt][nt], a[0][mt], b[nt]);
            }
        }
    }

    // ---- epilogue: paired stores (n, n+1)
#pragma unroll
    for (int mt = 0; mt < 2; mt++) {
#pragma unroll
        for (int nt = 0; nt < 8; nt++) {
#pragma unroll
            for (int half = 0; half < 2; half++) {
                int m = m0 + wm * 32 + mt * 16 + (lane >> 2) + half * 8;
                if (m >= M) continue;
                int n = n0 + wn * 64 + nt * 8 + (lane & 3) * 2;
                if (n >= N) continue;
                float v0 = d[mt][nt][half * 2 + 0];
                float v1 = d[mt][nt][half * 2 + 1];
                if (EPI & EPI_SCORE) { v0 = 2.f * v0 - vec[n]; v1 = 2.f * v1 - vec[n + 1]; }
                if (EPI & EPI_BIAS)  { v0 += bias[n]; v1 += bias[n + 1]; }
                if (EPI & EPI_RELU)  { v0 = fmaxf(v0, 0.f); v1 = fmaxf(v1, 0.f); }
                size_t o = (size_t)m * N + n;
                if (EPI & EPI_RESID) {
                    float2 rr = *(const float2*)(resid + o);
                    v0 += rr.x; v1 += rr.y;
                }
                if (EPI & EPI_YLAB) {
                    float rsc = rowscale[m];
                    v0 += rsc * vec[n] + bias[n];
                    v1 += rsc * vec[n + 1] + bias[n + 1];
                }
                if (OUTF32) *(float2*)(C + o) = make_float2(v0, v1);
                if (OUTPL == 2) {
                    h16 a0, b0h, a1, b1h;
                    split2h(v0, a0, b0h); split2h(v1, a1, b1h);
                    *(__half2*)(P0 + o) = __halves2half2(a0, a1);
                    *(__half2*)(P1 + o) = __halves2half2(b0h, b1h);
                }
                if (OUTPL == 1) {
                    __half2 hv = __floats2half2_rn(v0, v1);
                    stcs_u32(P0 + o, *(uint32_t*)&hv);   // streaming: S is read-once
                }
            }
        }
    }
}

template <int NPROD, int EPI, int OUTF32, int OUTPL>
static void launch_tgemm(const h16* A0, const h16* A1,
                         const h16* B0, const h16* B1,
                         float* C, h16* P0, h16* P1,
                         int M, int N, int K,
                         const float* bias = nullptr, const float* resid = nullptr,
                         const float* rowscale = nullptr, const float* vec = nullptr)
{
    constexpr int NPA = (NPROD == 3) ? 2 : 1;
    constexpr int NPB = (NPROD >= 2) ? 2 : 1;
    constexpr int SMEMB = 3 * (NPA + NPB) * PLANE_BYTES;
    cudaFuncSetAttribute(tgemm<NPROD, EPI, OUTF32, OUTPL>,
                         cudaFuncAttributeMaxDynamicSharedMemorySize, SMEMB);
    dim3 grid((N + 127) / 128, (M + 127) / 128);
    tgemm<NPROD, EPI, OUTF32, OUTPL><<<grid, 256, SMEMB>>>(
        A0, A1, B0, B1, C, P0, P1, M, N, K, bias, resid, rowscale, vec);
}

// ---------------------------------------------------------------------------
// Fused weight prep: 7 weight matrices W[K][N] fp32 -> 2 planes [N][K].
// Total blocks = 128+512+256+512+512+512+512 = 2944.
// ---------------------------------------------------------------------------
__global__ __launch_bounds__(256)
void wprep_all(const float* __restrict__ lin_w, h16* __restrict__ wlin,
               const float* __restrict__ b0_w2, h16* __restrict__ wb02,
               const float* __restrict__ K_w,   h16* __restrict__ wK,
               const float* __restrict__ T_w1,  h16* __restrict__ wT1,
               const float* __restrict__ T_w2,  h16* __restrict__ wT2,
               const float* __restrict__ p_w1,  h16* __restrict__ wp1,
               const float* __restrict__ p_w2,  h16* __restrict__ wp2)
{
    int blk = blockIdx.x;
#define WJOB(NBLK, W, P, Kd, Nd)                                              \
    if (blk < (NBLK)) {                                                       \
        int i = blk * 256 + threadIdx.x;                                      \
        if (i < (Kd) * (Nd)) {                                                \
            int n = i / (Kd), k = i % (Kd);                                   \
            float x = (W)[(size_t)k * (Nd) + n];                              \
            h16 a, b; split2h(x, a, b);                                       \
            (P)[i] = a; (P)[i + (Kd) * (Nd)] = b;                             \
        }                                                                     \
        return;                                                               \
    }                                                                         \
    blk -= (NBLK);
    WJOB(128, lin_w, wlin, D_IN, D_MAIN)
    WJOB(512, b0_w2, wb02, D_BLOCK, D_MAIN)
    WJOB(256, K_w, wK, D_MAIN, D_MAIN)
    WJOB(512, T_w1, wT1, D_MAIN, D_BLOCK)
    WJOB(512, T_w2, wT2, D_BLOCK, D_MAIN)
    WJOB(512, p_w1, wp1, D_MAIN, D_BLOCK)
    WJOB(512, p_w2, wp2, D_BLOCK, D_MAIN)
#undef WJOB
}
#define WPREP_BLOCKS 2944

// W_fuse = lin_w @ b0_w1 (fp32), planes [512][128]; b_fuse = lin_b@b0_w1 + b0_b1.
__global__ __launch_bounds__(128)
void wfuse_kernel(const float* __restrict__ lin_w, const float* __restrict__ lin_b,
                  const float* __restrict__ b0_w1, const float* __restrict__ b0_b1,
                  h16* __restrict__ wf0, h16* __restrict__ wf1,
                  float* __restrict__ bfuse)
{
    __shared__ float col[D_MAIN];
    int n = blockIdx.x;            // 0..511
    int k = threadIdx.x;           // 0..127
    for (int j = k; j < D_MAIN; j += 128) col[j] = b0_w1[(size_t)j * D_BLOCK + n];
    __syncthreads();
    float acc = 0.f;
    const float* lw = lin_w + (size_t)k * D_MAIN;
#pragma unroll 8
    for (int j = 0; j < D_MAIN; j++) acc = fmaf(lw[j], col[j], acc);
    h16 a, b; split2h(acc, a, b);
    wf0[n * D_IN + k] = a;
    wf1[n * D_IN + k] = b;
    if (k == 0) {
        float s = b0_b1[n];
        for (int j = 0; j < D_MAIN; j++) s = fmaf(lin_b[j], col[j], s);
        bfuse[n] = s;
    }
}

__global__ __launch_bounds__(256)
void split2_kernel(const float* __restrict__ x, h16* __restrict__ p0,
                   h16* __restrict__ p1, size_t n)
{
    size_t i = (size_t)blockIdx.x * blockDim.x + threadIdx.x;
    size_t st = (size_t)gridDim.x * blockDim.x;
    for (; i < n; i += st) {
        h16 a, b; split2h(x[i], a, b);
        p0[i] = a; p1[i] = b;
    }
}

// Warp-per-row LayerNorm (256-wide rows), 2 output planes.
__global__ __launch_bounds__(256)
void ln_warp(const float* __restrict__ X, const float* __restrict__ g,
             const float* __restrict__ b, h16* __restrict__ p0,
             h16* __restrict__ p1, int rows)
{
    int w = threadIdx.x >> 5, lane = threadIdx.x & 31;
    int row = blockIdx.x * 8 + w;
    if (row >= rows) return;
    const float4* xr = (const float4*)(X + (size_t)row * D_MAIN);
    float4 v0 = xr[lane * 2], v1 = xr[lane * 2 + 1];
    float x[8] = {v0.x, v0.y, v0.z, v0.w, v1.x, v1.y, v1.z, v1.w};
    float s = 0.f, ss = 0.f;
#pragma unroll
    for (int i = 0; i < 8; i++) { s += x[i]; ss = fmaf(x[i], x[i], ss); }
#pragma unroll
    for (int o = 16; o; o >>= 1) {
        s  += __shfl_xor_sync(0xFFFFFFFFu, s, o);
        ss += __shfl_xor_sync(0xFFFFFFFFu, ss, o);
    }
    float mean = s * (1.f / 256.f);
    float var  = ss * (1.f / 256.f) - mean * mean;
    float rs = rsqrtf(var + 1e-5f);
    const float4* gr = (const float4*)(g + lane * 8);
    const float4* br = (const float4*)(b + lane * 8);
    float4 g0 = gr[0], g1 = gr[1], b0 = br[0], b1 = br[1];
    float gg[8] = {g0.x, g0.y, g0.z, g0.w, g1.x, g1.y, g1.z, g1.w};
    float bb[8] = {b0.x, b0.y, b0.z, b0.w, b1.x, b1.y, b1.z, b1.w};
    __align__(16) h16 o0[8], o1[8];
#pragma unroll
    for (int i = 0; i < 8; i++) {
        float y = (x[i] - mean) * rs * gg[i] + bb[i];
        split2h(y, o0[i], o1[i]);
    }
    size_t off = (size_t)row * D_MAIN + lane * 8;
    *(uint4*)(p0 + off) = *(uint4*)&o0[0];
    *(uint4*)(p1 + off) = *(uint4*)&o1[0];
}

__global__ __launch_bounds__(256)
void rownorm_kernel(const float* __restrict__ X, float* __restrict__ nrm, int M)
{
    int row = blockIdx.x * 8 + (threadIdx.x >> 5);
    if (row >= M) return;
    int lane = threadIdx.x & 31;
    const float* xr = X + (size_t)row * D_MAIN;
    float s = 0.f;
#pragma unroll
    for (int i = 0; i < 8; i++) { float t = xr[lane + i * 32]; s = fmaf(t, t, s); }
#pragma unroll
    for (int o = 16; o; o >>= 1) s += __shfl_down_sync(0xFFFFFFFFu, s, o);
    if (lane == 0) nrm[row] = s;
}

// ---------------------------------------------------------------------------
// Screening on fp16 scores: 14-bit histogram (of 16-bit ordkeys) + collect.
// Vectorized streaming uint4 reads (8 keys/load). Emits everything above the
// boundary bin plus the whole bin (cap NSCR). N_CAND = 12500 * 8 exactly.
// ---------------------------------------------------------------------------
#define SCREEN_SMEM (16384 * 4 + NSCR * 4)
#define NV_ROW (N_CAND / 8)

__global__ __launch_bounds__(256)
void screen16_kernel(const h16* __restrict__ S, int* __restrict__ idxOut,
                     int* __restrict__ cntOut)
{
    extern __shared__ uint32_t shm[];
    uint32_t* hist = shm;          // 16384 bins (okey16 >> 2)
    uint32_t* tieI = shm + 16384;  // NSCR
    __shared__ uint32_t s_chunk[256];
    __shared__ int s_bin, s_out, s_tie;

    const int b = blockIdx.x, tid = threadIdx.x;
    const uint4* rowv = (const uint4*)(S + (size_t)b * N_CAND);

    for (int i = tid; i < 16384; i += 256) hist[i] = 0;
    __syncthreads();
    for (int i = tid; i < NV_ROW; i += 256) {
        uint4 v = __ldcs(rowv + i);
        uint32_t w[4] = {v.x, v.y, v.z, v.w};
#pragma unroll
        for (int q = 0; q < 4; q++) {
            atomicAdd(&hist[okey16u((uint16_t)(w[q] & 0xFFFFu)) >> 2], 1u);
            atomicAdd(&hist[okey16u((uint16_t)(w[q] >> 16)) >> 2], 1u);
        }
    }
    __syncthreads();
    uint32_t cs = 0;
#pragma unroll
    for (int j = 0; j < 64; j++) cs += hist[tid * 64 + j];
    s_chunk[tid] = cs;
    __syncthreads();
    if (tid == 0) {
        int cum = 0;
        for (int c = 255; c >= 0; c--) {
            if (cum + (int)s_chunk[c] >= 512) {
                for (int bin = c * 64 + 63; bin >= c * 64; bin--) {
                    int h = (int)hist[bin];
                    if (cum + h >= 512) { s_bin = bin; break; }
                    cum += h;
                }
                break;
            }
            cum += (int)s_chunk[c];
        }
        s_out = 0; s_tie = 0;
    }
    __syncthreads();

    const uint32_t bin = (uint32_t)s_bin;
    for (int i = tid; i < NV_ROW; i += 256) {
        uint4 v = __ldcs(rowv + i);
        uint32_t w[4] = {v.x, v.y, v.z, v.w};
#pragma unroll
        for (int q = 0; q < 4; q++) {
#pragma unroll
            for (int h = 0; h < 2; h++) {
                uint16_t hv = (h == 0) ? (uint16_t)(w[q] & 0xFFFFu)
                                       : (uint16_t)(w[q] >> 16);
                uint32_t k = okey16u(hv) >> 2;
                if (k > bin) {
                    int p = atomicAdd(&s_out, 1);
                    idxOut[b * NSCR + p] = i * 8 + q * 2 + h;
                } else if (k == bin) {
                    int p = atomicAdd(&s_tie, 1);
                    if (p < NSCR) tieI[p] = (uint32_t)(i * 8 + q * 2 + h);
                }
            }
        }
    }
    __syncthreads();
    int out = s_out;
    int take = s_tie < (NSCR - out) ? s_tie : (NSCR - out);
    for (int s = tid; s < take; s += 256)
        idxOut[b * NSCR + out + s] = (int)tieI[s];
    if (tid == 0) cntOut[b] = out + take;
}

// ---------------------------------------------------------------------------
// Exact fp32 rescore of survivors + exact top-96 (max score, tie -> min index)
// + fused softmax over the 96 selected scores (writes probs directly).
// ---------------------------------------------------------------------------
__global__ __launch_bounds__(256)
void rescore_kernel(const int* __restrict__ scr, const int* __restrict__ scrcnt,
                    const float* __restrict__ bk, const float* __restrict__ ck,
                    const float* __restrict__ cknorm,
                    int* __restrict__ idxOut, float* __restrict__ probs)
{
    __shared__ float kb[D_MAIN];
    __shared__ float sc[NSCR];
    __shared__ int   ids[NSCR];
    __shared__ float svs[CTX];
    __shared__ unsigned long long wbest[8];
    __shared__ unsigned long long s_win;
    __shared__ float sred[8];

    const int b = blockIdx.x, tid = threadIdx.x;
    const int wid = tid >> 5, lane = tid & 31;
    const int cnt = scrcnt[b];

    kb[tid] = bk[b * D_MAIN + tid];
    for (int j = tid; j < NSCR; j += 256) { sc[j] = -1e30f; ids[j] = 0x7FFFFFFF; }
    __syncthreads();

    for (int j = wid; j < cnt; j += 8) {
        int id = scr[b * NSCR + j];
        const float* cr = ck + (size_t)id * D_MAIN;
        float s = 0.f;
#pragma unroll
        for (int i = 0; i < 8; i++)
            s = fmaf(kb[lane + i * 32], cr[lane + i * 32], s);
#pragma unroll
        for (int o = 16; o; o >>= 1) s += __shfl_down_sync(0xFFFFFFFFu, s, o);
        if (lane == 0) { sc[j] = 2.f * s - cknorm[id]; ids[j] = id; }
    }
    __syncthreads();

    for (int r = 0; r < CTX; r++) {
        unsigned long long best = 0;
#pragma unroll
        for (int t = 0; t < NSCR / 256; t++) {
            int j = tid + t * 256;
            unsigned long long p = ((unsigned long long)ordkey(sc[j]) << 32)
                                 | (uint32_t)(0xFFFFFFFFu - (uint32_t)ids[j]);
            if (p > best) best = p;
        }
#pragma unroll
        for (int o = 16; o; o >>= 1) {
            unsigned long long q = __shfl_down_sync(0xFFFFFFFFu, best, o);
            if (q > best) best = q;
        }
        if (lane == 0) wbest[wid] = best;
        __syncthreads();
        if (tid == 0) {
            unsigned long long m = wbest[0];
#pragma unroll
            for (int i = 1; i < 8; i++) if (wbest[i] > m) m = wbest[i];
            s_win = m;
        }
        __syncthreads();
        unsigned long long win = s_win;
#pragma unroll
        for (int t = 0; t < NSCR / 256; t++) {
            int j = tid + t * 256;
            unsigned long long p = ((unsigned long long)ordkey(sc[j]) << 32)
                                 | (uint32_t)(0xFFFFFFFFu - (uint32_t)ids[j]);
            if (p == win) {
                idxOut[b * CTX + r] = ids[j];
                svs[r] = sc[j];
                sc[j] = -__int_as_float(0x7F800000);
            }
        }
        __syncthreads();
    }

    // ---- fused softmax over svs[0..95]
    float v = (tid < CTX) ? svs[tid] : -1e30f;
    float mx = v;
#pragma unroll
    for (int o = 16; o; o >>= 1) mx = fmaxf(mx, __shfl_xor_sync(0xFFFFFFFFu, mx, o));
    if (lane == 0) sred[wid] = mx;
    __syncthreads();
    if (tid == 0) {
        float m = sred[0];
#pragma unroll
        for (int i = 1; i < 8; i++) m = fmaxf(m, sred[i]);
        sred[0] = m;
    }
    __syncthreads();
    mx = sred[0];
    __syncthreads();
    float e = (tid < CTX) ? expf(v - mx) : 0.f;
    float sm = e;
#pragma unroll
    for (int o = 16; o; o >>= 1) sm += __shfl_xor_sync(0xFFFFFFFFu, sm, o);
    if (lane == 0) sred[wid] = sm;
    __syncthreads();
    if (tid == 0) {
        float m = 0.f;
#pragma unroll
        for (int i = 0; i < 8; i++) m += sred[i];
        sred[0] = m;
    }
    __syncthreads();
    if (tid < CTX) probs[b * CTX + tid] = e / sred[0];
}

// diff rows as single fp16 plane (half2 stores), plus y gather.
__global__ __launch_bounds__(128)
void build_diff(const int* __restrict__ idx, const float* __restrict__ bk,
                const float* __restrict__ ck, const float* __restrict__ cy,
                h16* __restrict__ dp0, float* __restrict__ yrow)
{
    int r = blockIdx.x, t = threadIdx.x;
    int b = r / CTX;
    int id = idx[r];
    float2 kb = *(const float2*)(bk + (size_t)b * D_MAIN + t * 2);
    float2 cc = *(const float2*)(ck + (size_t)id * D_MAIN + t * 2);
    *(__half2*)(dp0 + (size_t)r * D_MAIN + t * 2) =
        __floats2half2_rn(kb.x - cc.x, kb.y - cc.y);
    if (t == 0) yrow[r] = cy[id];
}

// R[b][2d..2d+1] = sum_c probs[b][c] * t1[b*96+c][2d..2d+1]; half2 loads.
__global__ __launch_bounds__(256)
void reduce_t(const float* __restrict__ probs, const h16* __restrict__ t1,
              const float* __restrict__ y, h16* __restrict__ R0,
              h16* __restrict__ R1, float* __restrict__ ysum)
{
    __shared__ float p[CTX];
    __shared__ float py[CTX];
    int b = blockIdx.x, d = threadIdx.x;       // d = column pair 0..255
    if (d < CTX) {
        float pv = probs[b * CTX + d];
        p[d] = pv;
        py[d] = pv * y[b * CTX + d];
    }
    __syncthreads();
    float acc0 = 0.f, acc1 = 0.f;
    const __half2* tb = (const __half2*)(t1 + (size_t)b * CTX * D_BLOCK) + d;
#pragma unroll 4
    for (int c = 0; c < CTX; c++) {
        float2 f = __half22float2(tb[(size_t)c * (D_BLOCK / 2)]);
        acc0 = fmaf(p[c], f.x, acc0);
        acc1 = fmaf(p[c], f.y, acc1);
    }
    h16 a0, b0h, a1, b1h;
    split2h(acc0, a0, b0h); split2h(acc1, a1, b1h);
    *(__half2*)(R0 + b * D_BLOCK + d * 2) = __halves2half2(a0, a1);
    *(__half2*)(R1 + b * D_BLOCK + d * 2) = __halves2half2(b0h, b1h);
    if (d == 0) {
        float s = 0.f;
        for (int c = 0; c < CTX; c++) s += py[c];
        ysum[b] = s;
    }
}

__device__ __forceinline__ float blk_sum256(float v, float* sh)
{
    int t = threadIdx.x;
#pragma unroll
    for (int o = 16; o; o >>= 1) v += __shfl_down_sync(0xFFFFFFFFu, v, o);
    if ((t & 31) == 0) sh[t >> 5] = v;
    __syncthreads();
    float tot = 0.f;
#pragma unroll
    for (int i = 0; i < 8; i++) tot += sh[i];
    __syncthreads();
    return tot;
}

__global__ __launch_bounds__(256)
void head_kernel(const float* __restrict__ X, const float* __restrict__ hg,
                 const float* __restrict__ hb, const float* __restrict__ hw,
                 const float* __restrict__ hb2, float* __restrict__ out)
{
    __shared__ float sh[8];
    int b = blockIdx.x, t = threadIdx.x;
    float v = X[(size_t)b * D_MAIN + t];
    float s  = blk_sum256(v, sh);
    float ss = blk_sum256(v * v, sh);
    float mean = s * (1.f / 256.f);
    float var  = ss * (1.f / 256.f) - mean * mean;
    float rs = rsqrtf(var + 1e-5f);
    float y = fmaxf((v - mean) * rs * hg[t] + hb[t], 0.f);
    float p = blk_sum256(y * hw[t], sh);
    if (t == 0) out[b] = p + hb2[0];
}

// ---------------------------------------------------------------------------
// Launch
// ---------------------------------------------------------------------------
template <typename T>
static inline T* sym(const void* s)
{
    void* p = nullptr;
    cudaGetSymbolAddress(&p, (const void*)s);
    return (T*)p;
}

extern "C" void kernel_launch(void* const* d_in, const int* in_sizes, int n_in,
                              void* d_out, int out_size)
{
    int wb = (in_sizes[3] == 1) ? 4 : 3;

    const float* x_num  = (const float*)d_in[0];
    const float* cand_x = (const float*)d_in[1];
    const float* cand_y = (const float*)d_in[2];
    const float* lin_w = (const float*)d_in[wb + 0];
    const float* lin_b = (const float*)d_in[wb + 1];
    const float* b0_w1 = (const float*)d_in[wb + 2];
    const float* b0_b1 = (const float*)d_in[wb + 3];
    const float* b0_w2 = (const float*)d_in[wb + 4];
    const float* b0_b2 = (const float*)d_in[wb + 5];
    const float* mix_g = (const float*)d_in[wb + 6];
    const float* mix_b = (const float*)d_in[wb + 7];
    const float* K_w   = (const float*)d_in[wb + 8];
    const float* K_b   = (const float*)d_in[wb + 9];
    const float* lab_w = (const float*)d_in[wb + 10];
    const float* lab_b = (const float*)d_in[wb + 11];
    const float* T_w1  = (const float*)d_in[wb + 12];
    const float* T_b1  = (const float*)d_in[wb + 13];
    const float* T_w2  = (const float*)d_in[wb + 14];
    const float* p_g   = (const float*)d_in[wb + 15];
    const float* p_b   = (const float*)d_in[wb + 16];
    const float* p_w1  = (const float*)d_in[wb + 17];
    const float* p_b1  = (const float*)d_in[wb + 18];
    const float* p_w2  = (const float*)d_in[wb + 19];
    const float* p_b2  = (const float*)d_in[wb + 20];
    const float* h_g   = (const float*)d_in[wb + 21];
    const float* h_b   = (const float*)d_in[wb + 22];
    const float* h_w   = (const float*)d_in[wb + 23];
    const float* h_b2  = (const float*)d_in[wb + 24];

    float* p_h1  = sym<float>(&g_h1);
    float* p_x2  = sym<float>(&g_x2);
    float* p_ck  = sym<float>(&g_ck);
    float* p_ckn = sym<float>(&g_cknorm);
    h16*   p_Sh  = sym<h16>(&g_Sh);
    float* p_x3  = sym<float>(&g_x3);
    float* p_x4  = sym<float>(&g_x4);
    int*   p_scr = sym<int>(&g_scr);
    int*   p_scn = sym<int>(&g_scrcnt);
    int*   p_idx = sym<int>(&g_idx);
    float* p_pr  = sym<float>(&g_probs);
    float* p_y   = sym<float>(&g_y);
    float* p_ys  = sym<float>(&g_ysum);
    float* p_bf  = sym<float>(&g_bfuse);

    h16* cxp  = sym<h16>(&g_cxp);
    h16* up   = sym<h16>(&g_up);
    h16* lnp  = sym<h16>(&g_lnp);
    h16* ckp  = sym<h16>(&g_ckp);
    h16* dfp  = sym<h16>(&g_dfp);
    h16* t1p  = sym<h16>(&g_t1p);
    h16* Rp   = sym<h16>(&g_Rp);
    h16* ln2p = sym<h16>(&g_ln2p);
    h16* ptp  = sym<h16>(&g_ptp);
    h16* wlin = sym<h16>(&g_wlin);
    h16* wfu  = sym<h16>(&g_wfuse);
    h16* wb02 = sym<h16>(&g_wb02);
    h16* wK   = sym<h16>(&g_wK);
    h16* wT1  = sym<h16>(&g_wT1);
    h16* wT2  = sym<h16>(&g_wT2);
    h16* wp1  = sym<h16>(&g_wp1);
    h16* wp2  = sym<h16>(&g_wp2);

    // batch-row views into the concatenated encode chain
    const float* p_bx2 = p_x2 + (size_t)N_CAND * D_MAIN;
    const float* p_bk  = p_ck + (size_t)N_CAND * D_MAIN;
    h16* bkp = ckp + (size_t)N_CAND * D_MAIN;

#define PL2(base, sz) (base), (base) + (sz)

    // ---- prep ----
    wprep_all<<<WPREP_BLOCKS, 256>>>(lin_w, wlin, b0_w2, wb02, K_w, wK,
                                     T_w1, wT1, T_w2, wT2, p_w1, wp1, p_w2, wp2);
    wfuse_kernel<<<D_BLOCK, 128>>>(lin_w, lin_b, b0_w1, b0_b1,
                                   PL2(wfu, D_BLOCK * D_IN), p_bf);
    split2_kernel<<<512, 256>>>(cand_x, cxp, cxp + (size_t)NTOT * D_IN,
                                (size_t)N_CAND * D_IN);
    split2_kernel<<<64, 256>>>(x_num, cxp + (size_t)N_CAND * D_IN,
                               cxp + (size_t)NTOT * D_IN + (size_t)N_CAND * D_IN,
                               (size_t)BATCH * D_IN);

    // ---- concatenated encode chain (candidates + batch, same weights) ----
    launch_tgemm<3, EPI_BIAS, 1, 0>(PL2(cxp, (size_t)NTOT * D_IN),
        PL2(wlin, D_MAIN * D_IN), p_h1, (h16*)nullptr, (h16*)nullptr,
        NTOT, D_MAIN, D_IN, lin_b);
    launch_tgemm<3, EPI_BIAS | EPI_RELU, 0, 2>(PL2(cxp, (size_t)NTOT * D_IN),
        PL2(wfu, D_BLOCK * D_IN), (float*)nullptr, PL2(up, (size_t)NTOT * D_BLOCK),
        NTOT, D_BLOCK, D_IN, p_bf);
    launch_tgemm<3, EPI_BIAS | EPI_RESID, 1, 0>(PL2(up, (size_t)NTOT * D_BLOCK),
        PL2(wb02, D_MAIN * D_BLOCK), p_x2, (h16*)nullptr, (h16*)nullptr,
        NTOT, D_MAIN, D_BLOCK, b0_b2, p_h1);
    ln_warp<<<(NTOT + 7) / 8, 256>>>(p_x2, mix_g, mix_b,
        PL2(lnp, (size_t)NTOT * D_MAIN), NTOT);
    launch_tgemm<3, EPI_BIAS, 1, 1>(PL2(lnp, (size_t)NTOT * D_MAIN),
        PL2(wK, D_MAIN * D_MAIN), p_ck, ckp, (h16*)nullptr,
        NTOT, D_MAIN, D_MAIN, K_b);
    rownorm_kernel<<<(N_CAND + 7) / 8, 256>>>(p_ck, p_ckn, N_CAND);

    // ---- KNN: 1-prod fp16 screen GEMM -> superset -> exact rescore top-96 ----
    launch_tgemm<1, EPI_SCORE, 0, 1>(bkp, (h16*)nullptr,
        ckp, (h16*)nullptr, (float*)nullptr, p_Sh, (h16*)nullptr,
        BATCH, N_CAND, D_MAIN, (const float*)nullptr, (const float*)nullptr,
        (const float*)nullptr, p_ckn);
    cudaFuncSetAttribute(screen16_kernel,
                         cudaFuncAttributeMaxDynamicSharedMemorySize, SCREEN_SMEM);
    screen16_kernel<<<BATCH, 256, SCREEN_SMEM>>>(p_Sh, p_scr, p_scn);
    rescore_kernel<<<BATCH, 256>>>(p_scr, p_scn, p_bk, p_ck, p_ckn, p_idx, p_pr);

    // ---- context values: T1 GEMM, weighted reduce, tiny T2 GEMM into x3 ----
    build_diff<<<NROWS_T, 128>>>(p_idx, p_bk, p_ck, cand_y, dfp, p_y);
    launch_tgemm<2, EPI_BIAS | EPI_RELU, 0, 1>(dfp, (h16*)nullptr,
        PL2(wT1, D_BLOCK * D_MAIN), (float*)nullptr, t1p, (h16*)nullptr,
        NROWS_T, D_BLOCK, D_MAIN, T_b1);
    reduce_t<<<BATCH, 256>>>(p_pr, t1p, p_y,
                             PL2(Rp, (size_t)BATCH * D_BLOCK), p_ys);
    launch_tgemm<3, EPI_RESID | EPI_YLAB, 1, 0>(PL2(Rp, (size_t)BATCH * D_BLOCK),
        PL2(wT2, D_MAIN * D_BLOCK), p_x3, (h16*)nullptr, (h16*)nullptr,
        BATCH, D_MAIN, D_BLOCK, lab_b, p_bx2, p_ys, lab_w);

    // ---- tail MLP + head ----
    ln_warp<<<(BATCH + 7) / 8, 256>>>(p_x3, p_g, p_b,
        PL2(ln2p, (size_t)BATCH * D_MAIN), BATCH);
    launch_tgemm<3, EPI_BIAS | EPI_RELU, 0, 2>(PL2(ln2p, (size_t)BATCH * D_MAIN),
        PL2(wp1, D_BLOCK * D_MAIN), (float*)nullptr, PL2(ptp, (size_t)BATCH * D_BLOCK),
        BATCH, D_BLOCK, D_MAIN, p_b1);
    launch_tgemm<3, EPI_BIAS | EPI_RESID, 1, 0>(PL2(ptp, (size_t)BATCH * D_BLOCK),
        PL2(wp2, D_MAIN * D_BLOCK), p_x4, (h16*)nullptr, (h16*)nullptr,
        BATCH, D_MAIN, D_BLOCK, p_b2, p_x3);
    head_kernel<<<BATCH, 256>>>(p_x4, h_g, h_b, h_w, h_b2, (float*)d_out);
}

// round 16
// speedup vs baseline: 1.0835x; 1.0835x over previous
#include <cuda_runtime.h>
#include <cuda_fp16.h>
#include <cstdint>

#define D_IN    128
#define D_MAIN  256
#define D_BLOCK 512
#define N_CAND  100000
#define BATCH   1024
#define NTOT    (N_CAND + BATCH)
#define CTX     96
#define NSCR    1024         // max survivors per row
#define NROWS_T (BATCH * CTX)

typedef __half h16;

// ---------------------------------------------------------------------------
// Scratch (static __device__ — no allocations allowed)
// ---------------------------------------------------------------------------
__device__ float g_h1 [NTOT * D_MAIN];
__device__ float g_x2 [NTOT * D_MAIN];
__device__ float g_ck [NTOT * D_MAIN];
__device__ float g_cknorm[N_CAND];
__device__ h16   g_Sh [BATCH * (size_t)N_CAND];
__device__ float g_x3 [BATCH * D_MAIN];
__device__ float g_x4 [BATCH * D_MAIN];
__device__ int   g_scr[BATCH * NSCR];
__device__ int   g_scrcnt[BATCH];
__device__ int   g_idx[BATCH * CTX];
__device__ float g_probs[BATCH * CTX];
__device__ float g_y  [NROWS_T];
__device__ float g_ysum[BATCH];
__device__ float g_bfuse[D_BLOCK];

// fp16 planes (single-plane where the consuming GEMM is 1/2-prod)
__device__ h16 g_cxp [NTOT * D_IN];          // 1 plane (2-prod lin/fused)
__device__ h16 g_up  [NTOT * D_BLOCK];       // 1 plane (2-prod b0w2)
__device__ h16 g_lnp [2][NTOT * D_MAIN];     // 2 planes (3-prod K)
__device__ h16 g_ckp [NTOT * D_MAIN];        // 1 plane (1-prod score)
__device__ h16 g_dfp [NROWS_T * D_MAIN];
__device__ h16 g_t1p [NROWS_T * D_BLOCK];
__device__ h16 g_Rp  [2][BATCH * D_BLOCK];
__device__ h16 g_ln2p[2][BATCH * D_MAIN];
__device__ h16 g_ptp [2][BATCH * D_BLOCK];

// weight planes, transposed to [N][K]
__device__ h16 g_wlin[2][D_MAIN * D_IN];
__device__ h16 g_wfuse[2][D_BLOCK * D_IN];
__device__ h16 g_wb02[2][D_MAIN * D_BLOCK];
__device__ h16 g_wK  [2][D_MAIN * D_MAIN];
__device__ h16 g_wT1 [2][D_BLOCK * D_MAIN];
__device__ h16 g_wT2 [2][D_MAIN * D_BLOCK];
__device__ h16 g_wp1 [2][D_BLOCK * D_MAIN];
__device__ h16 g_wp2 [2][D_MAIN * D_BLOCK];

// ---------------------------------------------------------------------------
// PTX helpers (sm_80+ — no 'a'-gated features)
// ---------------------------------------------------------------------------
__device__ __forceinline__ uint32_t smem_to_u32(const void* p) {
    uint32_t a;
    asm("{ .reg .u64 t; cvta.to.shared.u64 t, %1; cvt.u32.u64 %0, t; }"
        : "=r"(a) : "l"(p));
    return a;
}
__device__ __forceinline__ void ldsm_x4(uint32_t& r0, uint32_t& r1,
                                        uint32_t& r2, uint32_t& r3, uint32_t addr)
{
    asm volatile("ldmatrix.sync.aligned.m8n8.x4.shared.b16 {%0,%1,%2,%3}, [%4];"
                 : "=r"(r0), "=r"(r1), "=r"(r2), "=r"(r3) : "r"(addr));
}
__device__ __forceinline__ void mma16816(float* d, const uint32_t* a, const uint32_t* b)
{
    asm volatile("mma.sync.aligned.m16n8k16.row.col.f32.f16.f16.f32 "
                 "{%0,%1,%2,%3}, {%4,%5,%6,%7}, {%8,%9}, {%0,%1,%2,%3};"
                 : "+f"(d[0]), "+f"(d[1]), "+f"(d[2]), "+f"(d[3])
                 : "r"(a[0]), "r"(a[1]), "r"(a[2]), "r"(a[3]),
                   "r"(b[0]), "r"(b[1]));
}
__device__ __forceinline__ void cp_async16(uint32_t dst, const void* src, bool pred)
{
    int sz = pred ? 16 : 0;
    asm volatile("cp.async.cg.shared.global [%0], [%1], 16, %2;"
                 :: "r"(dst), "l"(src), "r"(sz) : "memory");
}
#define CP_COMMIT() asm volatile("cp.async.commit_group;" ::: "memory")
#define CP_WAIT1()  asm volatile("cp.async.wait_group 1;" ::: "memory")
#define CP_WAIT0()  asm volatile("cp.async.wait_group 0;" ::: "memory")

__device__ __forceinline__ void split2h(float x, h16& a, h16& b)
{
    a = __float2half_rn(x);
    b = __float2half_rn(x - __half2float(a));
}
__device__ __forceinline__ uint32_t ordkey(float f)
{
    uint32_t u = __float_as_uint(f);
    return (u & 0x80000000u) ? ~u : (u | 0x80000000u);
}
__device__ __forceinline__ uint32_t okey16u(uint16_t u)
{
    return (u & 0x8000u) ? (uint32_t)(0xFFFFu & ~u) : (uint32_t)(u | 0x8000u);
}
__device__ __forceinline__ void stcs_u32(void* p, uint32_t v)
{
    asm volatile("st.global.cs.u32 [%0], %1;" :: "l"(p), "r"(v) : "memory");
}

// ---------------------------------------------------------------------------
// HMMA split-fp16 GEMM: C[M,N] = A[M,K] @ B[N,K]^T.
// NPROD=3: a0b0+a0b1+a1b0 (~2^-22, A 2-plane); NPROD=2: a0(b0+b1) (~2^-12, A 1-plane);
// NPROD=1: a0b0 (plain fp16, screening grade; OUTPL=1 uses streaming stores).
// 128x128 tile, 8 warps (4x2), warp tile 32x64, BK=32, 3-stage cp.async ring.
// ---------------------------------------------------------------------------
enum { EPI_BIAS = 1, EPI_RELU = 2, EPI_RESID = 4, EPI_YLAB = 8, EPI_SCORE = 16 };

#define PLANE_BYTES 8192   // 128 rows * 64B

template <int NPROD, int EPI, int OUTF32, int OUTPL, int STREAMP0 = 0>
__global__ __launch_bounds__(256, 2)
void tgemm(const h16* __restrict__ A0, const h16* __restrict__ A1,
           const h16* __restrict__ B0, const h16* __restrict__ B1,
           float* __restrict__ C, h16* __restrict__ P0, h16* __restrict__ P1,
           int M, int N, int K,
           const float* __restrict__ bias, const float* __restrict__ resid,
           const float* __restrict__ rowscale, const float* __restrict__ vec)
{
    constexpr int NPA = (NPROD == 3) ? 2 : 1;
    constexpr int NPB = (NPROD >= 2) ? 2 : 1;
    constexpr int NPL = NPA + NPB;
    constexpr int STAGE = NPL * PLANE_BYTES;
    extern __shared__ __align__(16) char smem[];
    const uint32_t sb = smem_to_u32(smem);
    const int tid = threadIdx.x;
    const int wid = tid >> 5, lane = tid & 31;
    const int wm = wid & 3, wn = wid >> 2;
    const int m0 = blockIdx.y * 128, n0 = blockIdx.x * 128;

    const h16* Ap[2] = {A0, A1};
    const h16* Bp[2] = {B0, B1};

    float d[2][8][4];
#pragma unroll
    for (int i = 0; i < 2; i++)
#pragma unroll
        for (int j = 0; j < 8; j++)
#pragma unroll
            for (int e = 0; e < 4; e++) d[i][j][e] = 0.f;

    const int lrow = lane & 15;
    const int lhc  = lane >> 4;
    const int nch  = K >> 5;

    const int rA = tid >> 2, cA = tid & 3;
    auto load_tile = [&](int ch, int stg) {
        const int k0 = ch << 5;
        uint32_t base = sb + stg * STAGE;
#pragma unroll
        for (int it = 0; it < 2; it++) {
            int r = rA + it * 64;
            int sw = cA ^ ((r >> 1) & 3);
#pragma unroll
            for (int p = 0; p < NPA; p++) {
                int m = m0 + r;
                cp_async16(base + p * PLANE_BYTES + r * 64 + sw * 16,
                           Ap[p] + (size_t)m * K + k0 + cA * 8, m < M);
            }
#pragma unroll
            for (int q = 0; q < NPB; q++) {
                int n = n0 + r;
                cp_async16(base + (NPA + q) * PLANE_BYTES + r * 64 + sw * 16,
                           Bp[q] + (size_t)n * K + k0 + cA * 8, n < N);
            }
        }
    };

    load_tile(0, 0);
    CP_COMMIT();
    if (nch > 1) { load_tile(1, 1); CP_COMMIT(); }

    for (int ch = 0; ch < nch; ch++) {
        if (ch + 1 < nch) { CP_WAIT1(); } else { CP_WAIT0(); }
        __syncthreads();
        if (ch + 2 < nch) { load_tile(ch + 2, (ch + 2) % 3); CP_COMMIT(); }

        const uint32_t base = sb + (ch % 3) * STAGE;
#pragma unroll
        for (int ks = 0; ks < 2; ks++) {
            const int qc = ks * 2 + lhc;
            uint32_t a[NPA][2][4];
#pragma unroll
            for (int p = 0; p < NPA; p++)
#pragma unroll
                for (int mt = 0; mt < 2; mt++) {
                    int R = wm * 32 + mt * 16 + lrow;
                    int sw = qc ^ ((R >> 1) & 3);
                    ldsm_x4(a[p][mt][0], a[p][mt][1], a[p][mt][2], a[p][mt][3],
                            base + p * PLANE_BYTES + R * 64 + sw * 16);
                }
            uint32_t b[8][2];
#pragma unroll
            for (int ng = 0; ng < 4; ng++) {
                int R = wn * 64 + ng * 16 + lrow;
                int sw = qc ^ ((R >> 1) & 3);
                uint32_t q0, q1, q2, q3;
                ldsm_x4(q0, q1, q2, q3,
                        base + NPA * PLANE_BYTES + R * 64 + sw * 16);
                b[ng * 2 + 0][0] = q0; b[ng * 2 + 1][0] = q1;
                b[ng * 2 + 0][1] = q2; b[ng * 2 + 1][1] = q3;
            }
#pragma unroll
            for (int mt = 0; mt < 2; mt++)
#pragma unroll
                for (int nt = 0; nt < 8; nt++) {
                    mma16816(d[mt][nt], a[0][mt], b[nt]);
                    if (NPROD == 3) mma16816(d[mt][nt], a[1][mt], b[nt]);
                }
            if (NPROD >= 2) {
#pragma unroll
                for (int ng = 0; ng < 4; ng++) {
                    int R = wn * 64 + ng * 16 + lrow;
                    int sw = qc ^ ((R >> 1) & 3);
                    uint32_t q0, q1, q2, q3;
                    ldsm_x4(q0, q1, q2, q3,
                            base + (NPA + 1) * PLANE_BYTES + R * 64 + sw * 16);
                    b[ng * 2 + 0][0] = q0; b[ng * 2 + 1][0] = q1;
                    b[ng * 2 + 0][1] = q2; b[ng * 2 + 1][1] = q3;
                }
#pragma unroll
                for (int mt = 0; mt < 2; mt++)
#pragma unroll
                    for (int nt = 0; nt < 8; nt++)
                        mma16816(d[mt][nt], a[0][mt], b[nt]);
            }
        }
    }

    // ---- epilogue: paired stores (n, n+1)
#pragma unroll
    for (int mt = 0; mt < 2; mt++) {
#pragma unroll
        for (int nt = 0; nt < 8; nt++) {
#pragma unroll
            for (int half = 0; half < 2; half++) {
                int m = m0 + wm * 32 + mt * 16 + (lane >> 2) + half * 8;
                if (m >= M) continue;
                int n = n0 + wn * 64 + nt * 8 + (lane & 3) * 2;
                if (n >= N) continue;
                float v0 = d[mt][nt][half * 2 + 0];
                float v1 = d[mt][nt][half * 2 + 1];
                if (EPI & EPI_SCORE) { v0 = 2.f * v0 - vec[n]; v1 = 2.f * v1 - vec[n + 1]; }
                if (EPI & EPI_BIAS)  { v0 += bias[n]; v1 += bias[n + 1]; }
                if (EPI & EPI_RELU)  { v0 = fmaxf(v0, 0.f); v1 = fmaxf(v1, 0.f); }
                size_t o = (size_t)m * N + n;
                if (EPI & EPI_RESID) {
                    float2 rr = *(const float2*)(resid + o);
                    v0 += rr.x; v1 += rr.y;
                }
                if (EPI & EPI_YLAB) {
                    float rsc = rowscale[m];
                    v0 += rsc * vec[n] + bias[n];
                    v1 += rsc * vec[n + 1] + bias[n + 1];
                }
                if (OUTF32) *(float2*)(C + o) = make_float2(v0, v1);
                if (OUTPL == 2) {
                    h16 a0, b0h, a1, b1h;
                    split2h(v0, a0, b0h); split2h(v1, a1, b1h);
                    *(__half2*)(P0 + o) = __halves2half2(a0, a1);
                    *(__half2*)(P1 + o) = __halves2half2(b0h, b1h);
                }
                if (OUTPL == 1) {
                    __half2 hv = __floats2half2_rn(v0, v1);
                    if (STREAMP0) stcs_u32(P0 + o, *(uint32_t*)&hv);
                    else          *(__half2*)(P0 + o) = hv;
                }
            }
        }
    }
}

template <int NPROD, int EPI, int OUTF32, int OUTPL, int STREAMP0 = 0>
static void launch_tgemm(const h16* A0, const h16* A1,
                         const h16* B0, const h16* B1,
                         float* C, h16* P0, h16* P1,
                         int M, int N, int K,
                         const float* bias = nullptr, const float* resid = nullptr,
                         const float* rowscale = nullptr, const float* vec = nullptr)
{
    constexpr int NPA = (NPROD == 3) ? 2 : 1;
    constexpr int NPB = (NPROD >= 2) ? 2 : 1;
    constexpr int SMEMB = 3 * (NPA + NPB) * PLANE_BYTES;
    cudaFuncSetAttribute(tgemm<NPROD, EPI, OUTF32, OUTPL, STREAMP0>,
                         cudaFuncAttributeMaxDynamicSharedMemorySize, SMEMB);
    dim3 grid((N + 127) / 128, (M + 127) / 128);
    tgemm<NPROD, EPI, OUTF32, OUTPL, STREAMP0><<<grid, 256, SMEMB>>>(
        A0, A1, B0, B1, C, P0, P1, M, N, K, bias, resid, rowscale, vec);
}

// ---------------------------------------------------------------------------
// Fused weight prep: 7 weight matrices W[K][N] fp32 -> 2 planes [N][K].
// Total blocks = 128+512+256+512+512+512+512 = 2944.
// ---------------------------------------------------------------------------
__global__ __launch_bounds__(256)
void wprep_all(const float* __restrict__ lin_w, h16* __restrict__ wlin,
               const float* __restrict__ b0_w2, h16* __restrict__ wb02,
               const float* __restrict__ K_w,   h16* __restrict__ wK,
               const float* __restrict__ T_w1,  h16* __restrict__ wT1,
               const float* __restrict__ T_w2,  h16* __restrict__ wT2,
               const float* __restrict__ p_w1,  h16* __restrict__ wp1,
               const float* __restrict__ p_w2,  h16* __restrict__ wp2)
{
    int blk = blockIdx.x;
#define WJOB(NBLK, W, P, Kd, Nd)                                              \
    if (blk < (NBLK)) {                                                       \
        int i = blk * 256 + threadIdx.x;                                      \
        if (i < (Kd) * (Nd)) {                                                \
            int n = i / (Kd), k = i % (Kd);                                   \
            float x = (W)[(size_t)k * (Nd) + n];                              \
            h16 a, b; split2h(x, a, b);                                       \
            (P)[i] = a; (P)[i + (Kd) * (Nd)] = b;                             \
        }                                                                     \
        return;                                                               \
    }                                                                         \
    blk -= (NBLK);
    WJOB(128, lin_w, wlin, D_IN, D_MAIN)
    WJOB(512, b0_w2, wb02, D_BLOCK, D_MAIN)
    WJOB(256, K_w, wK, D_MAIN, D_MAIN)
    WJOB(512, T_w1, wT1, D_MAIN, D_BLOCK)
    WJOB(512, T_w2, wT2, D_BLOCK, D_MAIN)
    WJOB(512, p_w1, wp1, D_MAIN, D_BLOCK)
    WJOB(512, p_w2, wp2, D_BLOCK, D_MAIN)
#undef WJOB
}
#define WPREP_BLOCKS 2944

// W_fuse = lin_w @ b0_w1 (fp32), planes [512][128]; b_fuse = lin_b@b0_w1 + b0_b1.
__global__ __launch_bounds__(128)
void wfuse_kernel(const float* __restrict__ lin_w, const float* __restrict__ lin_b,
                  const float* __restrict__ b0_w1, const float* __restrict__ b0_b1,
                  h16* __restrict__ wf0, h16* __restrict__ wf1,
                  float* __restrict__ bfuse)
{
    __shared__ float col[D_MAIN];
    int n = blockIdx.x;            // 0..511
    int k = threadIdx.x;           // 0..127
    for (int j = k; j < D_MAIN; j += 128) col[j] = b0_w1[(size_t)j * D_BLOCK + n];
    __syncthreads();
    float acc = 0.f;
    const float* lw = lin_w + (size_t)k * D_MAIN;
#pragma unroll 8
    for (int j = 0; j < D_MAIN; j++) acc = fmaf(lw[j], col[j], acc);
    h16 a, b; split2h(acc, a, b);
    wf0[n * D_IN + k] = a;
    wf1[n * D_IN + k] = b;
    if (k == 0) {
        float s = b0_b1[n];
        for (int j = 0; j < D_MAIN; j++) s = fmaf(lin_b[j], col[j], s);
        bfuse[n] = s;
    }
}

// plain fp32 -> fp16 convert (single plane)
__global__ __launch_bounds__(256)
void f2h_kernel(const float* __restrict__ x, h16* __restrict__ p0, size_t n)
{
    size_t i = (size_t)blockIdx.x * blockDim.x + threadIdx.x;
    size_t st = (size_t)gridDim.x * blockDim.x;
    for (; i < n; i += st) p0[i] = __float2half_rn(x[i]);
}

// Warp-per-row LayerNorm (256-wide rows), 2 output planes.
__global__ __launch_bounds__(256)
void ln_warp(const float* __restrict__ X, const float* __restrict__ g,
             const float* __restrict__ b, h16* __restrict__ p0,
             h16* __restrict__ p1, int rows)
{
    int w = threadIdx.x >> 5, lane = threadIdx.x & 31;
    int row = blockIdx.x * 8 + w;
    if (row >= rows) return;
    const float4* xr = (const float4*)(X + (size_t)row * D_MAIN);
    float4 v0 = xr[lane * 2], v1 = xr[lane * 2 + 1];
    float x[8] = {v0.x, v0.y, v0.z, v0.w, v1.x, v1.y, v1.z, v1.w};
    float s = 0.f, ss = 0.f;
#pragma unroll
    for (int i = 0; i < 8; i++) { s += x[i]; ss = fmaf(x[i], x[i], ss); }
#pragma unroll
    for (int o = 16; o; o >>= 1) {
        s  += __shfl_xor_sync(0xFFFFFFFFu, s, o);
        ss += __shfl_xor_sync(0xFFFFFFFFu, ss, o);
    }
    float mean = s * (1.f / 256.f);
    float var  = ss * (1.f / 256.f) - mean * mean;
    float rs = rsqrtf(var + 1e-5f);
    const float4* gr = (const float4*)(g + lane * 8);
    const float4* br = (const float4*)(b + lane * 8);
    float4 g0 = gr[0], g1 = gr[1], b0 = br[0], b1 = br[1];
    float gg[8] = {g0.x, g0.y, g0.z, g0.w, g1.x, g1.y, g1.z, g1.w};
    float bb[8] = {b0.x, b0.y, b0.z, b0.w, b1.x, b1.y, b1.z, b1.w};
    __align__(16) h16 o0[8], o1[8];
#pragma unroll
    for (int i = 0; i < 8; i++) {
        float y = (x[i] - mean) * rs * gg[i] + bb[i];
        split2h(y, o0[i], o1[i]);
    }
    size_t off = (size_t)row * D_MAIN + lane * 8;
    *(uint4*)(p0 + off) = *(uint4*)&o0[0];
    *(uint4*)(p1 + off) = *(uint4*)&o1[0];
}

__global__ __launch_bounds__(256)
void rownorm_kernel(const float* __restrict__ X, float* __restrict__ nrm, int M)
{
    int row = blockIdx.x * 8 + (threadIdx.x >> 5);
    if (row >= M) return;
    int lane = threadIdx.x & 31;
    const float* xr = X + (size_t)row * D_MAIN;
    float s = 0.f;
#pragma unroll
    for (int i = 0; i < 8; i++) { float t = xr[lane + i * 32]; s = fmaf(t, t, s); }
#pragma unroll
    for (int o = 16; o; o >>= 1) s += __shfl_down_sync(0xFFFFFFFFu, s, o);
    if (lane == 0) nrm[row] = s;
}

// ---------------------------------------------------------------------------
// Screening on fp16 scores: 14-bit histogram (of 16-bit ordkeys) + collect.
// Vectorized streaming uint4 reads (8 keys/load). Emits everything above the
// boundary bin plus the whole bin (cap NSCR). N_CAND = 12500 * 8 exactly.
// ---------------------------------------------------------------------------
#define SCREEN_SMEM (16384 * 4 + NSCR * 4)
#define NV_ROW (N_CAND / 8)

__global__ __launch_bounds__(256)
void screen16_kernel(const h16* __restrict__ S, int* __restrict__ idxOut,
                     int* __restrict__ cntOut)
{
    extern __shared__ uint32_t shm[];
    uint32_t* hist = shm;          // 16384 bins (okey16 >> 2)
    uint32_t* tieI = shm + 16384;  // NSCR
    __shared__ uint32_t s_chunk[256];
    __shared__ int s_bin, s_out, s_tie;

    const int b = blockIdx.x, tid = threadIdx.x;
    const uint4* rowv = (const uint4*)(S + (size_t)b * N_CAND);

    for (int i = tid; i < 16384; i += 256) hist[i] = 0;
    __syncthreads();
    for (int i = tid; i < NV_ROW; i += 256) {
        uint4 v = __ldcs(rowv + i);
        uint32_t w[4] = {v.x, v.y, v.z, v.w};
#pragma unroll
        for (int q = 0; q < 4; q++) {
            atomicAdd(&hist[okey16u((uint16_t)(w[q] & 0xFFFFu)) >> 2], 1u);
            atomicAdd(&hist[okey16u((uint16_t)(w[q] >> 16)) >> 2], 1u);
        }
    }
    __syncthreads();
    uint32_t cs = 0;
#pragma unroll
    for (int j = 0; j < 64; j++) cs += hist[tid * 64 + j];
    s_chunk[tid] = cs;
    __syncthreads();
    if (tid == 0) {
        int cum = 0;
        for (int c = 255; c >= 0; c--) {
            if (cum + (int)s_chunk[c] >= 512) {
                for (int bin = c * 64 + 63; bin >= c * 64; bin--) {
                    int h = (int)hist[bin];
                    if (cum + h >= 512) { s_bin = bin; break; }
                    cum += h;
                }
                break;
            }
            cum += (int)s_chunk[c];
        }
        s_out = 0; s_tie = 0;
    }
    __syncthreads();

    const uint32_t bin = (uint32_t)s_bin;
    for (int i = tid; i < NV_ROW; i += 256) {
        uint4 v = __ldcs(rowv + i);
        uint32_t w[4] = {v.x, v.y, v.z, v.w};
#pragma unroll
        for (int q = 0; q < 4; q++) {
#pragma unroll
            for (int h = 0; h < 2; h++) {
                uint16_t hv = (h == 0) ? (uint16_t)(w[q] & 0xFFFFu)
                                       : (uint16_t)(w[q] >> 16);
                uint32_t k = okey16u(hv) >> 2;
                if (k > bin) {
                    int p = atomicAdd(&s_out, 1);
                    idxOut[b * NSCR + p] = i * 8 + q * 2 + h;
                } else if (k == bin) {
                    int p = atomicAdd(&s_tie, 1);
                    if (p < NSCR) tieI[p] = (uint32_t)(i * 8 + q * 2 + h);
                }
            }
        }
    }
    __syncthreads();
    int out = s_out;
    int take = s_tie < (NSCR - out) ? s_tie : (NSCR - out);
    for (int s = tid; s < take; s += 256)
        idxOut[b * NSCR + out + s] = (int)tieI[s];
    if (tid == 0) cntOut[b] = out + take;
}

// ---------------------------------------------------------------------------
// Exact fp32 rescore of survivors + exact top-96 (max score, tie -> min index)
// + fused softmax over the 96 selected scores (writes probs directly).
// ---------------------------------------------------------------------------
__global__ __launch_bounds__(256)
void rescore_kernel(const int* __restrict__ scr, const int* __restrict__ scrcnt,
                    const float* __restrict__ bk, const float* __restrict__ ck,
                    const float* __restrict__ cknorm,
                    int* __restrict__ idxOut, float* __restrict__ probs)
{
    __shared__ float kb[D_MAIN];
    __shared__ float sc[NSCR];
    __shared__ int   ids[NSCR];
    __shared__ float svs[CTX];
    __shared__ unsigned long long wbest[8];
    __shared__ unsigned long long s_win;
    __shared__ float sred[8];

    const int b = blockIdx.x, tid = threadIdx.x;
    const int wid = tid >> 5, lane = tid & 31;
    const int cnt = scrcnt[b];

    kb[tid] = bk[b * D_MAIN + tid];
    for (int j = tid; j < NSCR; j += 256) { sc[j] = -1e30f; ids[j] = 0x7FFFFFFF; }
    __syncthreads();

    for (int j = wid; j < cnt; j += 8) {
        int id = scr[b * NSCR + j];
        const float* cr = ck + (size_t)id * D_MAIN;
        float s = 0.f;
#pragma unroll
        for (int i = 0; i < 8; i++)
            s = fmaf(kb[lane + i * 32], cr[lane + i * 32], s);
#pragma unroll
        for (int o = 16; o; o >>= 1) s += __shfl_down_sync(0xFFFFFFFFu, s, o);
        if (lane == 0) { sc[j] = 2.f * s - cknorm[id]; ids[j] = id; }
    }
    __syncthreads();

    for (int r = 0; r < CTX; r++) {
        unsigned long long best = 0;
#pragma unroll
        for (int t = 0; t < NSCR / 256; t++) {
            int j = tid + t * 256;
            unsigned long long p = ((unsigned long long)ordkey(sc[j]) << 32)
                                 | (uint32_t)(0xFFFFFFFFu - (uint32_t)ids[j]);
            if (p > best) best = p;
        }
#pragma unroll
        for (int o = 16; o; o >>= 1) {
            unsigned long long q = __shfl_down_sync(0xFFFFFFFFu, best, o);
            if (q > best) best = q;
        }
        if (lane == 0) wbest[wid] = best;
        __syncthreads();
        if (tid == 0) {
            unsigned long long m = wbest[0];
#pragma unroll
            for (int i = 1; i < 8; i++) if (wbest[i] > m) m = wbest[i];
            s_win = m;
        }
        __syncthreads();
        unsigned long long win = s_win;
#pragma unroll
        for (int t = 0; t < NSCR / 256; t++) {
            int j = tid + t * 256;
            unsigned long long p = ((unsigned long long)ordkey(sc[j]) << 32)
                                 | (uint32_t)(0xFFFFFFFFu - (uint32_t)ids[j]);
            if (p == win) {
                idxOut[b * CTX + r] = ids[j];
                svs[r] = sc[j];
                sc[j] = -__int_as_float(0x7F800000);
            }
        }
        __syncthreads();
    }

    // ---- fused softmax over svs[0..95]
    float v = (tid < CTX) ? svs[tid] : -1e30f;
    float mx = v;
#pragma unroll
    for (int o = 16; o; o >>= 1) mx = fmaxf(mx, __shfl_xor_sync(0xFFFFFFFFu, mx, o));
    if (lane == 0) sred[wid] = mx;
    __syncthreads();
    if (tid == 0) {
        float m = sred[0];
#pragma unroll
        for (int i = 1; i < 8; i++) m = fmaxf(m, sred[i]);
        sred[0] = m;
    }
    __syncthreads();
    mx = sred[0];
    __syncthreads();
    float e = (tid < CTX) ? expf(v - mx) : 0.f;
    float sm = e;
#pragma unroll
    for (int o = 16; o; o >>= 1) sm += __shfl_xor_sync(0xFFFFFFFFu, sm, o);
    if (lane == 0) sred[wid] = sm;
    __syncthreads();
    if (tid == 0) {
        float m = 0.f;
#pragma unroll
        for (int i = 0; i < 8; i++) m += sred[i];
        sred[0] = m;
    }
    __syncthreads();
    if (tid < CTX) probs[b * CTX + tid] = e / sred[0];
}

// diff rows as single fp16 plane (half2 stores), plus y gather.
__global__ __launch_bounds__(128)
void build_diff(const int* __restrict__ idx, const float* __restrict__ bk,
                const float* __restrict__ ck, const float* __restrict__ cy,
                h16* __restrict__ dp0, float* __restrict__ yrow)
{
    int r = blockIdx.x, t = threadIdx.x;
    int b = r / CTX;
    int id = idx[r];
    float2 kb = *(const float2*)(bk + (size_t)b * D_MAIN + t * 2);
    float2 cc = *(const float2*)(ck + (size_t)id * D_MAIN + t * 2);
    *(__half2*)(dp0 + (size_t)r * D_MAIN + t * 2) =
        __floats2half2_rn(kb.x - cc.x, kb.y - cc.y);
    if (t == 0) yrow[r] = cy[id];
}

// R[b][2d..2d+1] = sum_c probs[b][c] * t1[b*96+c][2d..2d+1]; half2 loads.
__global__ __launch_bounds__(256)
void reduce_t(const float* __restrict__ probs, const h16* __restrict__ t1,
              const float* __restrict__ y, h16* __restrict__ R0,
              h16* __restrict__ R1, float* __restrict__ ysum)
{
    __shared__ float p[CTX];
    __shared__ float py[CTX];
    int b = blockIdx.x, d = threadIdx.x;       // d = column pair 0..255
    if (d < CTX) {
        float pv = probs[b * CTX + d];
        p[d] = pv;
        py[d] = pv * y[b * CTX + d];
    }
    __syncthreads();
    float acc0 = 0.f, acc1 = 0.f;
    const __half2* tb = (const __half2*)(t1 + (size_t)b * CTX * D_BLOCK) + d;
#pragma unroll 4
    for (int c = 0; c < CTX; c++) {
        float2 f = __half22float2(tb[(size_t)c * (D_BLOCK / 2)]);
        acc0 = fmaf(p[c], f.x, acc0);
        acc1 = fmaf(p[c], f.y, acc1);
    }
    h16 a0, b0h, a1, b1h;
    split2h(acc0, a0, b0h); split2h(acc1, a1, b1h);
    *(__half2*)(R0 + b * D_BLOCK + d * 2) = __halves2half2(a0, a1);
    *(__half2*)(R1 + b * D_BLOCK + d * 2) = __halves2half2(b0h, b1h);
    if (d == 0) {
        float s = 0.f;
        for (int c = 0; c < CTX; c++) s += py[c];
        ysum[b] = s;
    }
}

__device__ __forceinline__ float blk_sum256(float v, float* sh)
{
    int t = threadIdx.x;
#pragma unroll
    for (int o = 16; o; o >>= 1) v += __shfl_down_sync(0xFFFFFFFFu, v, o);
    if ((t & 31) == 0) sh[t >> 5] = v;
    __syncthreads();
    float tot = 0.f;
#pragma unroll
    for (int i = 0; i < 8; i++) tot += sh[i];
    __syncthreads();
    return tot;
}

__global__ __launch_bounds__(256)
void head_kernel(const float* __restrict__ X, const float* __restrict__ hg,
                 const float* __restrict__ hb, const float* __restrict__ hw,
                 const float* __restrict__ hb2, float* __restrict__ out)
{
    __shared__ float sh[8];
    int b = blockIdx.x, t = threadIdx.x;
    float v = X[(size_t)b * D_MAIN + t];
    float s  = blk_sum256(v, sh);
    float ss = blk_sum256(v * v, sh);
    float mean = s * (1.f / 256.f);
    float var  = ss * (1.f / 256.f) - mean * mean;
    float rs = rsqrtf(var + 1e-5f);
    float y = fmaxf((v - mean) * rs * hg[t] + hb[t], 0.f);
    float p = blk_sum256(y * hw[t], sh);
    if (t == 0) out[b] = p + hb2[0];
}

// ---------------------------------------------------------------------------
// Launch
// ---------------------------------------------------------------------------
template <typename T>
static inline T* sym(const void* s)
{
    void* p = nullptr;
    cudaGetSymbolAddress(&p, (const void*)s);
    return (T*)p;
}

extern "C" void kernel_launch(void* const* d_in, const int* in_sizes, int n_in,
                              void* d_out, int out_size)
{
    int wb = (in_sizes[3] == 1) ? 4 : 3;

    const float* x_num  = (const float*)d_in[0];
    const float* cand_x = (const float*)d_in[1];
    const float* cand_y = (const float*)d_in[2];
    const float* lin_w = (const float*)d_in[wb + 0];
    const float* lin_b = (const float*)d_in[wb + 1];
    const float* b0_w1 = (const float*)d_in[wb + 2];
    const float* b0_b1 = (const float*)d_in[wb + 3];
    const float* b0_w2 = (const float*)d_in[wb + 4];
    const float* b0_b2 = (const float*)d_in[wb + 5];
    const float* mix_g = (const float*)d_in[wb + 6];
    const float* mix_b = (const float*)d_in[wb + 7];
    const float* K_w   = (const float*)d_in[wb + 8];
    const float* K_b   = (const float*)d_in[wb + 9];
    const float* lab_w = (const float*)d_in[wb + 10];
    const float* lab_b = (const float*)d_in[wb + 11];
    const float* T_w1  = (const float*)d_in[wb + 12];
    const float* T_b1  = (const float*)d_in[wb + 13];
    const float* T_w2  = (const float*)d_in[wb + 14];
    const float* p_g   = (const float*)d_in[wb + 15];
    const float* p_b   = (const float*)d_in[wb + 16];
    const float* p_w1  = (const float*)d_in[wb + 17];
    const float* p_b1  = (const float*)d_in[wb + 18];
    const float* p_w2  = (const float*)d_in[wb + 19];
    const float* p_b2  = (const float*)d_in[wb + 20];
    const float* h_g   = (const float*)d_in[wb + 21];
    const float* h_b   = (const float*)d_in[wb + 22];
    const float* h_w   = (const float*)d_in[wb + 23];
    const float* h_b2  = (const float*)d_in[wb + 24];

    float* p_h1  = sym<float>(&g_h1);
    float* p_x2  = sym<float>(&g_x2);
    float* p_ck  = sym<float>(&g_ck);
    float* p_ckn = sym<float>(&g_cknorm);
    h16*   p_Sh  = sym<h16>(&g_Sh);
    float* p_x3  = sym<float>(&g_x3);
    float* p_x4  = sym<float>(&g_x4);
    int*   p_scr = sym<int>(&g_scr);
    int*   p_scn = sym<int>(&g_scrcnt);
    int*   p_idx = sym<int>(&g_idx);
    float* p_pr  = sym<float>(&g_probs);
    float* p_y   = sym<float>(&g_y);
    float* p_ys  = sym<float>(&g_ysum);
    float* p_bf  = sym<float>(&g_bfuse);

    h16* cxp  = sym<h16>(&g_cxp);
    h16* up   = sym<h16>(&g_up);
    h16* lnp  = sym<h16>(&g_lnp);
    h16* ckp  = sym<h16>(&g_ckp);
    h16* dfp  = sym<h16>(&g_dfp);
    h16* t1p  = sym<h16>(&g_t1p);
    h16* Rp   = sym<h16>(&g_Rp);
    h16* ln2p = sym<h16>(&g_ln2p);
    h16* ptp  = sym<h16>(&g_ptp);
    h16* wlin = sym<h16>(&g_wlin);
    h16* wfu  = sym<h16>(&g_wfuse);
    h16* wb02 = sym<h16>(&g_wb02);
    h16* wK   = sym<h16>(&g_wK);
    h16* wT1  = sym<h16>(&g_wT1);
    h16* wT2  = sym<h16>(&g_wT2);
    h16* wp1  = sym<h16>(&g_wp1);
    h16* wp2  = sym<h16>(&g_wp2);

    // batch-row views into the concatenated encode chain
    const float* p_bx2 = p_x2 + (size_t)N_CAND * D_MAIN;
    const float* p_bk  = p_ck + (size_t)N_CAND * D_MAIN;
    h16* bkp = ckp + (size_t)N_CAND * D_MAIN;

#define PL2(base, sz) (base), (base) + (sz)

    // ---- prep ----
    wprep_all<<<WPREP_BLOCKS, 256>>>(lin_w, wlin, b0_w2, wb02, K_w, wK,
                                     T_w1, wT1, T_w2, wT2, p_w1, wp1, p_w2, wp2);
    wfuse_kernel<<<D_BLOCK, 128>>>(lin_w, lin_b, b0_w1, b0_b1,
                                   PL2(wfu, D_BLOCK * D_IN), p_bf);
    f2h_kernel<<<512, 256>>>(cand_x, cxp, (size_t)N_CAND * D_IN);
    f2h_kernel<<<64, 256>>>(x_num, cxp + (size_t)N_CAND * D_IN, (size_t)BATCH * D_IN);

    // ---- concatenated encode chain (2-prod pre-LN, 3-prod K) ----
    launch_tgemm<2, EPI_BIAS, 1, 0>(cxp, (h16*)nullptr,
        PL2(wlin, D_MAIN * D_IN), p_h1, (h16*)nullptr, (h16*)nullptr,
        NTOT, D_MAIN, D_IN, lin_b);
    launch_tgemm<2, EPI_BIAS | EPI_RELU, 0, 1>(cxp, (h16*)nullptr,
        PL2(wfu, D_BLOCK * D_IN), (float*)nullptr, up, (h16*)nullptr,
        NTOT, D_BLOCK, D_IN, p_bf);
    launch_tgemm<2, EPI_BIAS | EPI_RESID, 1, 0>(up, (h16*)nullptr,
        PL2(wb02, D_MAIN * D_BLOCK), p_x2, (h16*)nullptr, (h16*)nullptr,
        NTOT, D_MAIN, D_BLOCK, b0_b2, p_h1);
    ln_warp<<<(NTOT + 7) / 8, 256>>>(p_x2, mix_g, mix_b,
        PL2(lnp, (size_t)NTOT * D_MAIN), NTOT);
    launch_tgemm<3, EPI_BIAS, 1, 1>(PL2(lnp, (size_t)NTOT * D_MAIN),
        PL2(wK, D_MAIN * D_MAIN), p_ck, ckp, (h16*)nullptr,
        NTOT, D_MAIN, D_MAIN, K_b);
    rownorm_kernel<<<(N_CAND + 7) / 8, 256>>>(p_ck, p_ckn, N_CAND);

    // ---- KNN: 1-prod fp16 screen GEMM -> superset -> exact rescore top-96 ----
    launch_tgemm<1, EPI_SCORE, 0, 1, 1>(bkp, (h16*)nullptr,
        ckp, (h16*)nullptr, (float*)nullptr, p_Sh, (h16*)nullptr,
        BATCH, N_CAND, D_MAIN, (const float*)nullptr, (const float*)nullptr,
        (const float*)nullptr, p_ckn);
    cudaFuncSetAttribute(screen16_kernel,
                         cudaFuncAttributeMaxDynamicSharedMemorySize, SCREEN_SMEM);
    screen16_kernel<<<BATCH, 256, SCREEN_SMEM>>>(p_Sh, p_scr, p_scn);
    rescore_kernel<<<BATCH, 256>>>(p_scr, p_scn, p_bk, p_ck, p_ckn, p_idx, p_pr);

    // ---- context values: T1 GEMM, weighted reduce, tiny T2 GEMM into x3 ----
    build_diff<<<NROWS_T, 128>>>(p_idx, p_bk, p_ck, cand_y, dfp, p_y);
    launch_tgemm<2, EPI_BIAS | EPI_RELU, 0, 1>(dfp, (h16*)nullptr,
        PL2(wT1, D_BLOCK * D_MAIN), (float*)nullptr, t1p, (h16*)nullptr,
        NROWS_T, D_BLOCK, D_MAIN, T_b1);
    reduce_t<<<BATCH, 256>>>(p_pr, t1p, p_y,
                             PL2(Rp, (size_t)BATCH * D_BLOCK), p_ys);
    launch_tgemm<3, EPI_RESID | EPI_YLAB, 1, 0>(PL2(Rp, (size_t)BATCH * D_BLOCK),
        PL2(wT2, D_MAIN * D_BLOCK), p_x3, (h16*)nullptr, (h16*)nullptr,
        BATCH, D_MAIN, D_BLOCK, lab_b, p_bx2, p_ys, lab_w);

    // ---- tail MLP + head ----
    ln_warp<<<(BATCH + 7) / 8, 256>>>(p_x3, p_g, p_b,
        PL2(ln2p, (size_t)BATCH * D_MAIN), BATCH);
    launch_tgemm<3, EPI_BIAS | EPI_RELU, 0, 2>(PL2(ln2p, (size_t)BATCH * D_MAIN),
        PL2(wp1, D_BLOCK * D_MAIN), (float*)nullptr, PL2(ptp, (size_t)BATCH * D_BLOCK),
        BATCH, D_BLOCK, D_MAIN, p_b1);
    launch_tgemm<3, EPI_BIAS | EPI_RESID, 1, 0>(PL2(ptp, (size_t)BATCH * D_BLOCK),
        PL2(wp2, D_MAIN * D_BLOCK), p_x4, (h16*)nullptr, (h16*)nullptr,
        BATCH, D_MAIN, D_BLOCK, p_b2, p_x3);
    head_kernel<<<BATCH, 256>>>(p_x4, h_g, h_b, h_w, h_b2, (float*)d_out);
}